// round 1
// baseline (speedup 1.0000x reference)
#include <cuda_runtime.h>
#include <math.h>

#define Bb 4
#define Nn 32
#define Mm 64
#define Kk 16
#define K1 17
#define Pp 128
#define Ww 128
#define TWd 256

// ------- scratch (device globals; no runtime allocation) -------
__device__ float d_A[Bb*Nn*K1*TWd];     // layer-0 partial incl. x, vall, coeff, tb0
__device__ float d_Bm[Bb*Mm*TWd];       // layer-0 partial from xp, vp
__device__ float d_sw0T[Ww*Ww];         // sw0 transposed: [w][i]
__device__ float d_sw1T[Ww*Ww];
__device__ float d_gdot[Bb*Nn*Mm];

// =====================================================================
// K1: attention MLP + softmax + coeff + A-partial.  One block per (b,n,k1).
// 128 threads = one per p.
// =====================================================================
__global__ void __launch_bounds__(128) k1_attn(
    const float* __restrict__ phase,   // (B,N,4)
    const float* __restrict__ posc,    // (B,P,2)
    const float* __restrict__ sigma,   // (B,P,2)
    const float* __restrict__ velc,    // (B,K,2)
    const float* __restrict__ aw0, const float* __restrict__ ab0,
    const float* __restrict__ aw1, const float* __restrict__ ab1,
    const float* __restrict__ aw2, const float* __restrict__ ab2,
    const float* __restrict__ tw0, const float* __restrict__ tb0)
{
    __shared__ float s_aw0[6*64];
    __shared__ float s_ab0[64];
    __shared__ float s_aw1T[64*64];  // [i][j] = aw1[j][i]
    __shared__ float s_aw2[64];
    __shared__ float red[128];

    const int bx = blockIdx.x;               // 0..2175
    const int k1 = bx % K1;
    const int n  = (bx / K1) % Nn;
    const int b  = bx / (K1*Nn);
    const int t  = threadIdx.x;              // p

    for (int i = t; i < 6*64; i += 128) s_aw0[i] = aw0[i];
    if (t < 64) { s_ab0[t] = ab0[t]; s_aw2[t] = aw2[t]; }
    for (int i = t; i < 64*64; i += 128) {
        int j = i >> 6, c = i & 63;
        s_aw1T[c*64 + j] = aw1[i];
    }
    __syncthreads();

    const float x0 = phase[(b*Nn+n)*4 + 0];
    const float x1 = phase[(b*Nn+n)*4 + 1];
    float va0, va1;
    if (k1 == 0) { va0 = phase[(b*Nn+n)*4 + 2]; va1 = phase[(b*Nn+n)*4 + 3]; }
    else         { va0 = velc[(b*Kk + (k1-1))*2 + 0]; va1 = velc[(b*Kk + (k1-1))*2 + 1]; }
    const float inv = rsqrtf(va0*va0 + va1*va1 + 1e-16f);
    const float ag0 = va0*inv, ag1 = va1*inv;

    const float rx = x0 - posc[(b*Pp + t)*2 + 0];
    const float ry = x1 - posc[(b*Pp + t)*2 + 1];
    const float rd = sqrtf(rx*rx + ry*ry + 1e-16f);
    const float pl = rx*ag0 + ry*ag1;          // pos_local
    const float al = pl / (rd + 1e-8f);        // ang_local

    // layer 0: 6 -> 64
    float h0[64];
#pragma unroll
    for (int j = 0; j < 64; j++) {
        h0[j] = tanhf(s_ab0[j] + x0*s_aw0[0*64+j] + x1*s_aw0[1*64+j]
                              + va0*s_aw0[2*64+j] + va1*s_aw0[3*64+j]
                              + al*s_aw0[4*64+j] + pl*s_aw0[5*64+j]);
    }
    // layers 1+2 fused: 64 -> 64 (tanh) -> 1
    float logit = ab2[0];
    for (int i = 0; i < 64; i++) {
        float a = ab1[i];
        const float4* row = reinterpret_cast<const float4*>(&s_aw1T[i*64]);
#pragma unroll
        for (int j4 = 0; j4 < 16; j4++) {
            float4 w4 = row[j4];
            a += h0[4*j4+0]*w4.x + h0[4*j4+1]*w4.y + h0[4*j4+2]*w4.z + h0[4*j4+3]*w4.w;
        }
        logit += tanhf(a) * s_aw2[i];
    }

    // masked softmax over p
    float lg = (pl > 0.0f) ? logit : -1e30f;
    red[t] = lg; __syncthreads();
    for (int s = 64; s > 0; s >>= 1) { if (t < s) red[t] = fmaxf(red[t], red[t+s]); __syncthreads(); }
    const float mx = red[0]; __syncthreads();
    const float e = expf(lg - mx);
    red[t] = e; __syncthreads();
    for (int s = 64; s > 0; s >>= 1) { if (t < s) red[t] += red[t+s]; __syncthreads(); }
    const float denom = red[0]; __syncthreads();
    const float aw = e / denom;

    const float sg0 = sigma[(b*Pp+t)*2 + 0];
    const float sg1 = sigma[(b*Pp+t)*2 + 1];
    red[t] = aw*sg0; __syncthreads();
    for (int s = 64; s > 0; s >>= 1) { if (t < s) red[t] += red[t+s]; __syncthreads(); }
    const float sum0 = red[0]; __syncthreads();
    red[t] = aw*sg1; __syncthreads();
    for (int s = 64; s > 0; s >>= 1) { if (t < s) red[t] += red[t+s]; __syncthreads(); }
    const float sum1 = red[0]; __syncthreads();

    const float c0 = expf(-sum0);
    const float c1 = expf(-sum1);

    // A[b,n,k1][0..255] = tb0 + x@tw0[0:2] + vall@tw0[2:4] + coeff@tw0[8:10]
    for (int tt = t; tt < TWd; tt += 128) {
        float a = tb0[tt]
                + x0*tw0[0*TWd+tt] + x1*tw0[1*TWd+tt]
                + va0*tw0[2*TWd+tt] + va1*tw0[3*TWd+tt]
                + c0*tw0[8*TWd+tt] + c1*tw0[9*TWd+tt];
        d_A[bx*TWd + tt] = a;
    }
}

// =====================================================================
// K_bm: Bm[b,m][0..255] = xp@tw0[4:6] + vp@tw0[6:8].  One block per (b,m).
// =====================================================================
__global__ void k_bm(const float* __restrict__ bcoords, const float* __restrict__ tw0)
{
    const int bm = blockIdx.x;   // b*64+m
    const int t  = threadIdx.x;  // 0..255
    const float xp0 = bcoords[bm*4+0], xp1 = bcoords[bm*4+1];
    const float vp0 = bcoords[bm*4+2], vp1 = bcoords[bm*4+3];
    d_Bm[bm*TWd + t] = xp0*tw0[4*TWd+t] + xp1*tw0[5*TWd+t]
                     + vp0*tw0[6*TWd+t] + vp1*tw0[7*TWd+t];
}

// transpose sw0/sw1 for coalesced column access
__global__ void k_tr(const float* __restrict__ sw0, const float* __restrict__ sw1)
{
    const int idx = blockIdx.x*256 + threadIdx.x;  // 0..16383
    const int i = idx >> 7, w = idx & 127;
    d_sw0T[w*Ww + i] = sw0[idx];
    d_sw1T[w*Ww + i] = sw1[idx];
}

// =====================================================================
// K4: transport MLP (layers 1,2) + full scattering chain, fused.
// One block per (b, n, chunk of 2 m).  256 threads.
// =====================================================================
#define K4_SMEM_FLOATS 13584
__global__ void __launch_bounds__(256) k4_main(
    const float* __restrict__ scat,   // (B,N,K)
    const float* __restrict__ sscat,  // (B,K,K)
    const float* __restrict__ vwt,    // (B,K)
    const float* __restrict__ tw1, const float* __restrict__ tb1,
    const float* __restrict__ tw2, const float* __restrict__ tb2,
    const float* __restrict__ sb0, const float* __restrict__ sb1,
    const float* __restrict__ out_w)
{
    extern __shared__ float sm[];
    float* h0s  = sm;             // 17*256
    float* h1s  = sm + 4352;      // 17*256
    float* gs   = sm + 8704;      // 17*128
    float* resv = sm + 10880;     // 128
    float* r2t  = sm + 11008;     // 128*16  (res2 transposed: [w][k])
    float* rwv  = sm + 13056;     // 16
    float* rwvs = sm + 13072;     // 16*16
    float* red  = sm + 13328;     // 256

    const int bx    = blockIdx.x;        // 0..4095
    const int chunk = bx & 31;           // 32 chunks of 2 m
    const int n     = (bx >> 5) & 31;
    const int b     = bx >> 10;
    const int t     = threadIdx.x;
    const int col   = t & 127;
    const int half  = t >> 7;

    if (t < 16) rwv[t] = (1.0f - scat[(b*Nn+n)*Kk + t]) * vwt[b*Kk + t];
    { const int j = t & 15; rwvs[t] = (1.0f - sscat[b*256 + t]) * vwt[b*Kk + j]; }
    __syncthreads();

    const float* Arow = d_A + (b*Nn + n)*K1*TWd;
    const float tb1t = tb1[t];
    const float tb2c = tb2[col];
    const float sb0c = sb0[col];

    for (int mm = 0; mm < 2; mm++) {
        const int m = chunk*2 + mm;

        // ---- layer 0: h0 = tanh(A + Bm) ----
        const float bmv = d_Bm[(b*Mm + m)*TWd + t];
#pragma unroll
        for (int k = 0; k < K1; k++)
            h0s[k*TWd + t] = tanhf(Arow[k*TWd + t] + bmv);
        __syncthreads();

        // ---- layer 1: h1 = tanh(h0 @ tw1 + tb1); thread = column t ----
        float acc[K1];
#pragma unroll
        for (int k = 0; k < K1; k++) acc[k] = 0.0f;
        for (int j = 0; j < TWd; j += 4) {
            const float w0 = tw1[(j+0)*TWd + t];
            const float w1 = tw1[(j+1)*TWd + t];
            const float w2 = tw1[(j+2)*TWd + t];
            const float w3 = tw1[(j+3)*TWd + t];
#pragma unroll
            for (int k = 0; k < K1; k++) {
                float4 h = *reinterpret_cast<const float4*>(&h0s[k*TWd + j]);
                acc[k] += h.x*w0 + h.y*w1 + h.z*w2 + h.w*w3;
            }
        }
#pragma unroll
        for (int k = 0; k < K1; k++) h1s[k*TWd + t] = tanhf(acc[k] + tb1t);
        __syncthreads();

        // ---- layer 2: g = exp(tanh(h1 @ tw2 + tb2)); thread = (col, row-half) ----
        const int base = half ? 9 : 0;
        const int cnt  = half ? 8 : 9;
        float acc2[9];
#pragma unroll
        for (int k = 0; k < 9; k++) acc2[k] = 0.0f;
        for (int j = 0; j < TWd; j += 4) {
            const float w0 = tw2[(j+0)*Ww + col];
            const float w1 = tw2[(j+1)*Ww + col];
            const float w2 = tw2[(j+2)*Ww + col];
            const float w3 = tw2[(j+3)*Ww + col];
#pragma unroll
            for (int k = 0; k < 9; k++) {
                if (k < cnt) {
                    float4 h = *reinterpret_cast<const float4*>(&h1s[(base+k)*TWd + j]);
                    acc2[k] += h.x*w0 + h.y*w1 + h.z*w2 + h.w*w3;
                }
            }
        }
#pragma unroll
        for (int k = 0; k < 9; k++)
            if (k < cnt) gs[(base+k)*Ww + col] = expf(tanhf(acc2[k] + tb2c));
        __syncthreads();

        // ---- scattering stage 1: res_v and res2 (from old g) ----
        {
            float rv = 0.0f;
            float r2[8];
#pragma unroll
            for (int kk = 0; kk < 8; kk++) r2[kk] = 0.0f;
#pragma unroll
            for (int j = 0; j < Kk; j++) {
                const float gv = gs[(1+j)*Ww + col];
                if (half == 0) rv += rwv[j]*gv;
#pragma unroll
                for (int kk = 0; kk < 8; kk++)
                    r2[kk] += rwvs[(half*8+kk)*Kk + j] * gv;
            }
            if (half == 0) resv[col] = rv;
#pragma unroll
            for (int kk = 0; kk < 8; kk++) r2t[col*Kk + half*8 + kk] = r2[kk];
        }
        __syncthreads();

        // ---- stage 2: new_v & vstar2 (in-place into gs) via sw0 ----
        {
            float s[8]; float s8 = 0.0f;
#pragma unroll
            for (int kk = 0; kk < 8; kk++) s[kk] = 0.0f;
            for (int w = 0; w < Ww; w++) {
                const float swv = d_sw0T[w*Ww + col];
                float4 ra = *reinterpret_cast<const float4*>(&r2t[w*Kk + half*8]);
                float4 rb = *reinterpret_cast<const float4*>(&r2t[w*Kk + half*8 + 4]);
                s[0] += swv*ra.x; s[1] += swv*ra.y; s[2] += swv*ra.z; s[3] += swv*ra.w;
                s[4] += swv*rb.x; s[5] += swv*rb.y; s[6] += swv*rb.z; s[7] += swv*rb.w;
                if (half == 0) s8 += swv * resv[w];
            }
#pragma unroll
            for (int kk = 0; kk < 8; kk++) {
                const int row = 1 + half*8 + kk;
                gs[row*Ww + col] += tanhf(s[kk] + sb0c);
            }
            if (half == 0) gs[col] += tanhf(s8 + sb0c);   // new_v into row 0
        }
        __syncthreads();

        // ---- stage 3: res_v2 from updated vstar ----
        if (half == 0) {
            float rv = 0.0f;
#pragma unroll
            for (int k = 0; k < Kk; k++) rv += rwv[k] * gs[(1+k)*Ww + col];
            resv[col] = rv;
        }
        __syncthreads();

        // ---- stage 4: green = new_v + tanh(sw1 @ res_v2 + sb1); gdot ----
        float part = 0.0f;
        if (half == 0) {
            float a = 0.0f;
            for (int w = 0; w < Ww; w++) a += d_sw1T[w*Ww + col] * resv[w];
            const float green = gs[col] + tanhf(a + sb1[col]);
            part = green * out_w[col];
        }
        red[t] = part;
        __syncthreads();
        for (int s = 128; s > 0; s >>= 1) { if (t < s) red[t] += red[t+s]; __syncthreads(); }
        if (t == 0) d_gdot[(b*Nn+n)*Mm + m] = red[0];
        __syncthreads();
    }
}

// =====================================================================
// K6: out[b,n] = sum_m gdot[b,n,m] * boundary[b,m] * boundary_weights[b,m]
// =====================================================================
__global__ void k6_final(const float* __restrict__ boundary,
                         const float* __restrict__ bweights,
                         float* __restrict__ out)
{
    const int t = threadIdx.x;   // 0..127 = b*32+n
    const int b = t >> 5;
    float s = 0.0f;
    for (int m = 0; m < Mm; m++)
        s += d_gdot[t*Mm + m] * boundary[b*Mm + m] * bweights[b*Mm + m];
    out[t] = s;
}

// =====================================================================
extern "C" void kernel_launch(void* const* d_in, const int* in_sizes, int n_in,
                              void* d_out, int out_size)
{
    const float* phase    = (const float*)d_in[0];
    const float* bcoords  = (const float*)d_in[1];
    const float* boundary = (const float*)d_in[2];
    const float* bweights = (const float*)d_in[3];
    const float* posc     = (const float*)d_in[4];
    const float* sigma    = (const float*)d_in[5];
    const float* velc     = (const float*)d_in[6];
    const float* vwt      = (const float*)d_in[7];
    const float* scat     = (const float*)d_in[8];
    const float* sscat    = (const float*)d_in[9];
    const float* aw0 = (const float*)d_in[10];
    const float* ab0 = (const float*)d_in[11];
    const float* aw1 = (const float*)d_in[12];
    const float* ab1 = (const float*)d_in[13];
    const float* aw2 = (const float*)d_in[14];
    const float* ab2 = (const float*)d_in[15];
    const float* tw0 = (const float*)d_in[16];
    const float* tb0 = (const float*)d_in[17];
    const float* tw1 = (const float*)d_in[18];
    const float* tb1 = (const float*)d_in[19];
    const float* tw2 = (const float*)d_in[20];
    const float* tb2 = (const float*)d_in[21];
    const float* sw0 = (const float*)d_in[22];
    const float* sb0 = (const float*)d_in[23];
    const float* sw1 = (const float*)d_in[24];
    const float* sb1 = (const float*)d_in[25];
    const float* ow  = (const float*)d_in[26];
    float* out = (float*)d_out;

    // opt-in to >48KB dynamic smem (host-side attribute set; not a stream op)
    cudaFuncSetAttribute(k4_main, cudaFuncAttributeMaxDynamicSharedMemorySize,
                         K4_SMEM_FLOATS * (int)sizeof(float));

    k1_attn<<<Bb*Nn*K1, 128>>>(phase, posc, sigma, velc,
                               aw0, ab0, aw1, ab1, aw2, ab2, tw0, tb0);
    k_bm<<<Bb*Mm, TWd>>>(bcoords, tw0);
    k_tr<<<64, 256>>>(sw0, sw1);
    k4_main<<<Bb*Nn*32, 256, K4_SMEM_FLOATS*(int)sizeof(float)>>>(
        scat, sscat, vwt, tw1, tb1, tw2, tb2, sb0, sb1, ow);
    k6_final<<<1, 128>>>(boundary, bweights, out);
}

// round 2
// speedup vs baseline: 1.1832x; 1.1832x over previous
#include <cuda_runtime.h>
#include <math.h>

#define Bb 4
#define Nn 32
#define Mm 64
#define Kk 16
#define K1 17
#define Pp 128
#define Ww 128
#define TWd 256

typedef unsigned long long ull;

// ---------- f32x2 helpers ----------
__device__ __forceinline__ ull pack2(float a, float b) {
    ull r; asm("mov.b64 %0, {%1, %2};" : "=l"(r) : "f"(a), "f"(b)); return r;
}
__device__ __forceinline__ void unpack2(ull v, float& a, float& b) {
    asm("mov.b64 {%0, %1}, %2;" : "=f"(a), "=f"(b) : "l"(v));
}
__device__ __forceinline__ void fma2(ull& d, ull a, ull b) {
    asm("fma.rn.f32x2 %0, %1, %2, %0;" : "+l"(d) : "l"(a), "l"(b));
}
__device__ __forceinline__ ull add2(ull a, ull b) {
    ull r; asm("add.rn.f32x2 %0, %1, %2;" : "=l"(r) : "l"(a), "l"(b)); return r;
}
// exact identity tanh = 1 - 2/(exp(2x)+1); only error is __expf rounding (~2^-21)
__device__ __forceinline__ float ftanh(float x) {
    float e = __expf(2.0f * x);
    return 1.0f - __fdividef(2.0f, e + 1.0f);
}

// ------- scratch (device globals; no runtime allocation) -------
__device__ float d_A[Bb*Nn*K1*TWd];     // layer-0 partial incl. x, vall, coeff, tb0
__device__ float d_Bm[Bb*Mm*TWd];       // layer-0 partial from xp, vp
__device__ float d_gdot[Bb*Nn*Mm];

// =====================================================================
// K1: attention MLP + softmax + coeff + A-partial.  One block per (b,n,k1).
// 128 threads = one per p.
// =====================================================================
__global__ void __launch_bounds__(128) k1_attn(
    const float* __restrict__ phase,   // (B,N,4)
    const float* __restrict__ posc,    // (B,P,2)
    const float* __restrict__ sigma,   // (B,P,2)
    const float* __restrict__ velc,    // (B,K,2)
    const float* __restrict__ aw0, const float* __restrict__ ab0,
    const float* __restrict__ aw1, const float* __restrict__ ab1,
    const float* __restrict__ aw2, const float* __restrict__ ab2,
    const float* __restrict__ tw0, const float* __restrict__ tb0)
{
    __shared__ float s_aw0[6*64];
    __shared__ float s_ab0[64];
    __shared__ float s_aw1[64*64];   // row-major [j][i] (as stored)
    __shared__ float s_ab1[64];
    __shared__ float s_aw2[64];
    __shared__ float red[128];

    const int bx = blockIdx.x;               // 0..2175
    const int k1 = bx % K1;
    const int n  = (bx / K1) % Nn;
    const int b  = bx / (K1*Nn);
    const int t  = threadIdx.x;              // p

    for (int i = t; i < 6*64; i += 128) s_aw0[i] = aw0[i];
    if (t < 64) { s_ab0[t] = ab0[t]; s_aw2[t] = aw2[t]; s_ab1[t] = ab1[t]; }
    for (int i = t; i < 64*64; i += 128) s_aw1[i] = aw1[i];
    __syncthreads();

    const float x0 = phase[(b*Nn+n)*4 + 0];
    const float x1 = phase[(b*Nn+n)*4 + 1];
    float va0, va1;
    if (k1 == 0) { va0 = phase[(b*Nn+n)*4 + 2]; va1 = phase[(b*Nn+n)*4 + 3]; }
    else         { va0 = velc[(b*Kk + (k1-1))*2 + 0]; va1 = velc[(b*Kk + (k1-1))*2 + 1]; }
    const float inv = rsqrtf(va0*va0 + va1*va1 + 1e-16f);
    const float ag0 = va0*inv, ag1 = va1*inv;

    const float rx = x0 - posc[(b*Pp + t)*2 + 0];
    const float ry = x1 - posc[(b*Pp + t)*2 + 1];
    const float rd = sqrtf(rx*rx + ry*ry + 1e-16f);
    const float pl = rx*ag0 + ry*ag1;          // pos_local
    const float al = pl / (rd + 1e-8f);        // ang_local

    // layer 0: 6 -> 64
    float h0[64];
#pragma unroll
    for (int j = 0; j < 64; j++) {
        h0[j] = ftanh(s_ab0[j] + x0*s_aw0[0*64+j] + x1*s_aw0[1*64+j]
                              + va0*s_aw0[2*64+j] + va1*s_aw0[3*64+j]
                              + al*s_aw0[4*64+j] + pl*s_aw0[5*64+j]);
    }
    // layers 1+2 fused, paired over output i: 64 -> 64 (tanh) -> 1
    float logit = ab2[0];
#pragma unroll
    for (int g = 0; g < 4; g++) {           // 16 i's per group (8 pairs)
        ull acc[8];
#pragma unroll
        for (int p = 0; p < 8; p++) acc[p] = 0ull;
        for (int j = 0; j < 64; j++) {
            const ull hp = pack2(h0[j], h0[j]);
            const float* wrow = &s_aw1[j*64 + g*16];
            ulonglong2 wA = *reinterpret_cast<const ulonglong2*>(wrow + 0);
            ulonglong2 wB = *reinterpret_cast<const ulonglong2*>(wrow + 4);
            ulonglong2 wC = *reinterpret_cast<const ulonglong2*>(wrow + 8);
            ulonglong2 wD = *reinterpret_cast<const ulonglong2*>(wrow + 12);
            fma2(acc[0], hp, wA.x); fma2(acc[1], hp, wA.y);
            fma2(acc[2], hp, wB.x); fma2(acc[3], hp, wB.y);
            fma2(acc[4], hp, wC.x); fma2(acc[5], hp, wC.y);
            fma2(acc[6], hp, wD.x); fma2(acc[7], hp, wD.y);
        }
#pragma unroll
        for (int p = 0; p < 8; p++) {
            const int i = g*16 + p*2;
            float a0, a1; unpack2(acc[p], a0, a1);
            logit += ftanh(a0 + s_ab1[i])   * s_aw2[i]
                   + ftanh(a1 + s_ab1[i+1]) * s_aw2[i+1];
        }
    }

    // masked softmax over p
    float lg = (pl > 0.0f) ? logit : -1e30f;
    red[t] = lg; __syncthreads();
    for (int s = 64; s > 0; s >>= 1) { if (t < s) red[t] = fmaxf(red[t], red[t+s]); __syncthreads(); }
    const float mx = red[0]; __syncthreads();
    const float e = __expf(lg - mx);
    red[t] = e; __syncthreads();
    for (int s = 64; s > 0; s >>= 1) { if (t < s) red[t] += red[t+s]; __syncthreads(); }
    const float denom = red[0]; __syncthreads();
    const float aw = e / denom;

    const float sg0 = sigma[(b*Pp+t)*2 + 0];
    const float sg1 = sigma[(b*Pp+t)*2 + 1];
    red[t] = aw*sg0; __syncthreads();
    for (int s = 64; s > 0; s >>= 1) { if (t < s) red[t] += red[t+s]; __syncthreads(); }
    const float sum0 = red[0]; __syncthreads();
    red[t] = aw*sg1; __syncthreads();
    for (int s = 64; s > 0; s >>= 1) { if (t < s) red[t] += red[t+s]; __syncthreads(); }
    const float sum1 = red[0]; __syncthreads();

    const float c0 = __expf(-sum0);
    const float c1 = __expf(-sum1);

    // A[b,n,k1][0..255] = tb0 + x@tw0[0:2] + vall@tw0[2:4] + coeff@tw0[8:10]
    for (int tt = t; tt < TWd; tt += 128) {
        float a = tb0[tt]
                + x0*tw0[0*TWd+tt] + x1*tw0[1*TWd+tt]
                + va0*tw0[2*TWd+tt] + va1*tw0[3*TWd+tt]
                + c0*tw0[8*TWd+tt] + c1*tw0[9*TWd+tt];
        d_A[bx*TWd + tt] = a;
    }
}

// =====================================================================
// K_bm: Bm[b,m][0..255] = xp@tw0[4:6] + vp@tw0[6:8].  One block per (b,m).
// =====================================================================
__global__ void k_bm(const float* __restrict__ bcoords, const float* __restrict__ tw0)
{
    const int bm = blockIdx.x;   // b*64+m
    const int t  = threadIdx.x;  // 0..255
    const float xp0 = bcoords[bm*4+0], xp1 = bcoords[bm*4+1];
    const float vp0 = bcoords[bm*4+2], vp1 = bcoords[bm*4+3];
    d_Bm[bm*TWd + t] = xp0*tw0[4*TWd+t] + xp1*tw0[5*TWd+t]
                     + vp0*tw0[6*TWd+t] + vp1*tw0[7*TWd+t];
}

// =====================================================================
// K4: transport MLP (layers 1,2) + full scattering chain, fused.
// One block per (b, n, m-pair). 256 threads. The two m's of the pair ride
// in the two lanes of f32x2 throughout. Single smem buffer reused:
// h0(m-interleaved) -> h1(m-interleaved) -> [g | rr] (pairs).
// =====================================================================
#define K4_SMEM_FLOATS (8704 + 544 + 256 + 512)
__global__ void __launch_bounds__(256) k4_main(
    const float* __restrict__ scat,   // (B,N,K)
    const float* __restrict__ sscat,  // (B,K,K)
    const float* __restrict__ vwt,    // (B,K)
    const float* __restrict__ tw1, const float* __restrict__ tb1,
    const float* __restrict__ tw2, const float* __restrict__ tb2,
    const float* __restrict__ sw0, const float* __restrict__ sb0,
    const float* __restrict__ sw1, const float* __restrict__ sb1,
    const float* __restrict__ out_w)
{
    extern __shared__ float sm[];
    float* buf  = sm;                         // 8704 floats (34KB), multi-purpose
    ull*   ws2  = (ull*)(sm + 8704);          // 272 dup-pairs (row0=rw_v, rows1..16=rw_vs)
    float* sres = sm + 8704 + 544;            // 128 pairs = 256 floats
    float* sred = sm + 8704 + 544 + 256;      // 256 pairs = 512 floats

    const int bx   = blockIdx.x;              // 0..4095
    const int pair = bx & 31;                 // m-pair index
    const int n    = (bx >> 5) & 31;
    const int b    = bx >> 10;
    const int t    = threadIdx.x;
    const int c    = t & 127;
    const int kh   = t >> 7;                  // also mi for layer0

    // scattering weight dup-pairs
    for (int i = t; i < 272; i += 256) {
        const int row = i >> 4, j = i & 15;
        float v = (row == 0) ? (1.0f - scat[(b*Nn+n)*Kk + j])
                             : (1.0f - sscat[b*256 + (row-1)*Kk + j]);
        v *= vwt[b*Kk + j];
        ws2[i] = pack2(v, v);
    }

    // ---- layer 0: h0[k][j][mi] = tanh(A[k][j] + Bm[m][j]) ----
    const float* Arow = d_A + (b*Nn + n)*K1*TWd;
    const float* bmp  = d_Bm + (b*Mm + pair*2 + kh)*TWd;
    {
        const float bm0 = bmp[c], bm1 = bmp[c+128];
#pragma unroll
        for (int k = 0; k < K1; k++) {
            buf[k*512 + c*2 + kh]         = ftanh(Arow[k*256 + c]       + bm0);
            buf[k*512 + (c+128)*2 + kh]   = ftanh(Arow[k*256 + c + 128] + bm1);
        }
    }
    __syncthreads();

    // ---- layer 1: h1 = tanh(h0 @ tw1 + tb1); thread = column t, both m in lanes ----
    {
        ull acc[K1];
#pragma unroll
        for (int k = 0; k < K1; k++) acc[k] = 0ull;
        for (int j = 0; j < TWd; j += 4) {
            const float* w = tw1 + j*TWd + t;
            const float w0 = w[0], w1 = w[TWd], w2 = w[2*TWd], w3 = w[3*TWd];
            const ull p0 = pack2(w0,w0), p1 = pack2(w1,w1), p2 = pack2(w2,w2), p3 = pack2(w3,w3);
#pragma unroll
            for (int k = 0; k < K1; k++) {
                ulonglong2 ha = *reinterpret_cast<const ulonglong2*>(buf + k*512 + j*2);
                ulonglong2 hb = *reinterpret_cast<const ulonglong2*>(buf + k*512 + j*2 + 4);
                fma2(acc[k], ha.x, p0); fma2(acc[k], ha.y, p1);
                fma2(acc[k], hb.x, p2); fma2(acc[k], hb.y, p3);
            }
        }
        __syncthreads();   // all h0 reads done -> safe to overwrite with h1
        const float tb1t = tb1[t];
#pragma unroll
        for (int k = 0; k < K1; k++) {
            float a0, a1; unpack2(acc[k], a0, a1);
            *reinterpret_cast<ull*>(buf + k*512 + t*2) = pack2(ftanh(a0+tb1t), ftanh(a1+tb1t));
        }
        __syncthreads();
    }

    // ---- layer 2: g = exp(tanh(h1 @ tw2 + tb2)); thread = (c, row-half kh) ----
    const int r0  = kh * 9;
    const int cnt = kh ? 8 : 9;
    {
        ull acc[9];
#pragma unroll
        for (int k = 0; k < 9; k++) acc[k] = 0ull;
        for (int j = 0; j < TWd; j += 4) {
            const float* w = tw2 + j*Ww + c;
            const float w0 = w[0], w1 = w[Ww], w2 = w[2*Ww], w3 = w[3*Ww];
            const ull p0 = pack2(w0,w0), p1 = pack2(w1,w1), p2 = pack2(w2,w2), p3 = pack2(w3,w3);
#pragma unroll
            for (int kk = 0; kk < 9; kk++) {
                if (kk < cnt) {
                    const int k = r0 + kk;
                    ulonglong2 ha = *reinterpret_cast<const ulonglong2*>(buf + k*512 + j*2);
                    ulonglong2 hb = *reinterpret_cast<const ulonglong2*>(buf + k*512 + j*2 + 4);
                    fma2(acc[kk], ha.x, p0); fma2(acc[kk], ha.y, p1);
                    fma2(acc[kk], hb.x, p2); fma2(acc[kk], hb.y, p3);
                }
            }
        }
        __syncthreads();   // all h1 reads done -> buf becomes [g | rr]
        const float tb2c = tb2[c];
#pragma unroll
        for (int kk = 0; kk < 9; kk++) {
            if (kk < cnt) {
                float a0, a1; unpack2(acc[kk], a0, a1);
                *reinterpret_cast<ull*>(buf + (r0+kk)*256 + c*2) =
                    pack2(__expf(ftanh(a0+tb2c)), __expf(ftanh(a1+tb2c)));
            }
        }
        __syncthreads();
    }

    // ---- stage 1: rr[0]=res_v, rr[1+i]=res2[i] from old g (rows 1..16) ----
    {
        ull r[9];
#pragma unroll
        for (int kk = 0; kk < 9; kk++) r[kk] = 0ull;
#pragma unroll
        for (int j = 0; j < Kk; j++) {
            const ull g2 = *reinterpret_cast<const ull*>(buf + (1+j)*256 + c*2);
#pragma unroll
            for (int kk = 0; kk < 9; kk++)
                if (kk < cnt) fma2(r[kk], g2, ws2[(r0+kk)*Kk + j]);
        }
#pragma unroll
        for (int kk = 0; kk < 9; kk++)
            if (kk < cnt) *reinterpret_cast<ull*>(buf + 4352 + (r0+kk)*256 + c*2) = r[kk];
        __syncthreads();
    }

    // ---- stage 2: g[row][c] += tanh(sum_w sw0[c][w]*rr[row][w] + sb0[c]) ----
    {
        ull s2[9];
#pragma unroll
        for (int kk = 0; kk < 9; kk++) s2[kk] = 0ull;
        const float* swr = sw0 + c*Ww;
        for (int w = 0; w < Ww; w += 4) {
            const float4 s4 = *reinterpret_cast<const float4*>(swr + w);
            const ull p0 = pack2(s4.x,s4.x), p1 = pack2(s4.y,s4.y),
                      p2 = pack2(s4.z,s4.z), p3 = pack2(s4.w,s4.w);
#pragma unroll
            for (int kk = 0; kk < 9; kk++) {
                if (kk < cnt) {
                    ulonglong2 ra = *reinterpret_cast<const ulonglong2*>(buf + 4352 + (r0+kk)*256 + w*2);
                    ulonglong2 rb = *reinterpret_cast<const ulonglong2*>(buf + 4352 + (r0+kk)*256 + w*2 + 4);
                    fma2(s2[kk], ra.x, p0); fma2(s2[kk], ra.y, p1);
                    fma2(s2[kk], rb.x, p2); fma2(s2[kk], rb.y, p3);
                }
            }
        }
        const float sb0c = sb0[c];
#pragma unroll
        for (int kk = 0; kk < 9; kk++) {
            if (kk < cnt) {
                float a0, a1; unpack2(s2[kk], a0, a1);
                ull* gp = reinterpret_cast<ull*>(buf + (r0+kk)*256 + c*2);
                float g0, g1; unpack2(*gp, g0, g1);
                *gp = pack2(g0 + ftanh(a0+sb0c), g1 + ftanh(a1+sb0c));
            }
        }
        __syncthreads();
    }

    // ---- stage 3: resv2[c] = sum_k rw_v[k] * g'[1+k][c] ----
    if (kh == 0) {
        ull rv = 0ull;
#pragma unroll
        for (int k = 0; k < Kk; k++)
            fma2(rv, *reinterpret_cast<const ull*>(buf + (1+k)*256 + c*2), ws2[k]);
        *reinterpret_cast<ull*>(sres + c*2) = rv;
    }
    __syncthreads();

    // ---- stage 4: green = g'[0] + tanh(sw1[c][:]@resv2 + sb1); gdot reduce ----
    {
        ull s4a = 0ull;
        const float* sw1r = sw1 + c*Ww + kh*64;
        const int wbase = kh*64;
        for (int w = 0; w < 64; w += 4) {
            const float4 v4 = *reinterpret_cast<const float4*>(sw1r + w);
            const ull p0 = pack2(v4.x,v4.x), p1 = pack2(v4.y,v4.y),
                      p2 = pack2(v4.z,v4.z), p3 = pack2(v4.w,v4.w);
            ulonglong2 ra = *reinterpret_cast<const ulonglong2*>(sres + (wbase+w)*2);
            ulonglong2 rb = *reinterpret_cast<const ulonglong2*>(sres + (wbase+w)*2 + 4);
            fma2(s4a, ra.x, p0); fma2(s4a, ra.y, p1);
            fma2(s4a, rb.x, p2); fma2(s4a, rb.y, p3);
        }
        *reinterpret_cast<ull*>(sred + t*2) = s4a;
        __syncthreads();
        float part0 = 0.0f, part1 = 0.0f;
        if (kh == 0) {
            const ull tot = add2(s4a, *reinterpret_cast<const ull*>(sred + (t+128)*2));
            float a0, a1; unpack2(tot, a0, a1);
            float v0, v1; unpack2(*reinterpret_cast<const ull*>(buf + c*2), v0, v1);
            const float sb1c = sb1[c], ow = out_w[c];
            part0 = (v0 + ftanh(a0+sb1c)) * ow;
            part1 = (v1 + ftanh(a1+sb1c)) * ow;
        }
        __syncthreads();
        *reinterpret_cast<ull*>(sred + t*2) = pack2(part0, part1);
        __syncthreads();
        for (int s = 64; s > 0; s >>= 1) {
            if (t < s) {
                ull x = add2(*reinterpret_cast<const ull*>(sred + t*2),
                             *reinterpret_cast<const ull*>(sred + (t+s)*2));
                *reinterpret_cast<ull*>(sred + t*2) = x;
            }
            __syncthreads();
        }
        if (t == 0) {
            float g0, g1; unpack2(*reinterpret_cast<const ull*>(sred), g0, g1);
            d_gdot[(b*Nn+n)*Mm + pair*2 + 0] = g0;
            d_gdot[(b*Nn+n)*Mm + pair*2 + 1] = g1;
        }
    }
}

// =====================================================================
// K6: out[b,n] = sum_m gdot[b,n,m] * boundary[b,m] * boundary_weights[b,m]
// =====================================================================
__global__ void k6_final(const float* __restrict__ boundary,
                         const float* __restrict__ bweights,
                         float* __restrict__ out)
{
    const int t = threadIdx.x;   // 0..127 = b*32+n
    const int b = t >> 5;
    float s = 0.0f;
    for (int m = 0; m < Mm; m++)
        s += d_gdot[t*Mm + m] * boundary[b*Mm + m] * bweights[b*Mm + m];
    out[t] = s;
}

// =====================================================================
extern "C" void kernel_launch(void* const* d_in, const int* in_sizes, int n_in,
                              void* d_out, int out_size)
{
    const float* phase    = (const float*)d_in[0];
    const float* bcoords  = (const float*)d_in[1];
    const float* boundary = (const float*)d_in[2];
    const float* bweights = (const float*)d_in[3];
    const float* posc     = (const float*)d_in[4];
    const float* sigma    = (const float*)d_in[5];
    const float* velc     = (const float*)d_in[6];
    const float* vwt      = (const float*)d_in[7];
    const float* scat     = (const float*)d_in[8];
    const float* sscat    = (const float*)d_in[9];
    const float* aw0 = (const float*)d_in[10];
    const float* ab0 = (const float*)d_in[11];
    const float* aw1 = (const float*)d_in[12];
    const float* ab1 = (const float*)d_in[13];
    const float* aw2 = (const float*)d_in[14];
    const float* ab2 = (const float*)d_in[15];
    const float* tw0 = (const float*)d_in[16];
    const float* tb0 = (const float*)d_in[17];
    const float* tw1 = (const float*)d_in[18];
    const float* tb1 = (const float*)d_in[19];
    const float* tw2 = (const float*)d_in[20];
    const float* tb2 = (const float*)d_in[21];
    const float* sw0 = (const float*)d_in[22];
    const float* sb0 = (const float*)d_in[23];
    const float* sw1 = (const float*)d_in[24];
    const float* sb1 = (const float*)d_in[25];
    const float* ow  = (const float*)d_in[26];
    float* out = (float*)d_out;

    k1_attn<<<Bb*Nn*K1, 128>>>(phase, posc, sigma, velc,
                               aw0, ab0, aw1, ab1, aw2, ab2, tw0, tb0);
    k_bm<<<Bb*Mm, TWd>>>(bcoords, tw0);
    k4_main<<<Bb*Nn*(Mm/2), 256, K4_SMEM_FLOATS*(int)sizeof(float)>>>(
        scat, sscat, vwt, tw1, tb1, tw2, tb2, sw0, sb0, sw1, sb1, ow);
    k6_final<<<1, 128>>>(boundary, bweights, out);
}

// round 3
// speedup vs baseline: 1.4994x; 1.2672x over previous
#include <cuda_runtime.h>
#include <math.h>

#define Bb 4
#define Nn 32
#define Mm 64
#define Kk 16
#define K1 17
#define Pp 128
#define Ww 128
#define TWd 256

typedef unsigned long long ull;

// ---------- f32x2 helpers ----------
__device__ __forceinline__ ull pack2(float a, float b) {
    ull r; asm("mov.b64 %0, {%1, %2};" : "=l"(r) : "f"(a), "f"(b)); return r;
}
__device__ __forceinline__ void unpack2(ull v, float& a, float& b) {
    asm("mov.b64 {%0, %1}, %2;" : "=f"(a), "=f"(b) : "l"(v));
}
__device__ __forceinline__ void fma2(ull& d, ull a, ull b) {
    asm("fma.rn.f32x2 %0, %1, %2, %0;" : "+l"(d) : "l"(a), "l"(b));
}
__device__ __forceinline__ ull add2(ull a, ull b) {
    ull r; asm("add.rn.f32x2 %0, %1, %2;" : "=l"(r) : "l"(a), "l"(b)); return r;
}
// exact identity tanh = 1 - 2/(exp(2x)+1); only error is __expf rounding (~2^-21)
__device__ __forceinline__ float ftanh(float x) {
    float e = __expf(2.0f * x);
    return 1.0f - __fdividef(2.0f, e + 1.0f);
}

// ------- scratch (device globals; no runtime allocation) -------
__device__ float d_A[Bb*Nn*K1*TWd];     // layer-0 partial incl. x, vall, coeff, tb0
__device__ float d_Bm[Bb*Mm*TWd];       // layer-0 partial from xp, vp
__device__ float d_gdot[Bb*Nn*Mm];

// =====================================================================
// K1: attention MLP + softmax + coeff + A-partial.  One block per (b,n,k1).
// 128 threads = one per p.
// =====================================================================
__global__ void __launch_bounds__(128) k1_attn(
    const float* __restrict__ phase,   // (B,N,4)
    const float* __restrict__ posc,    // (B,P,2)
    const float* __restrict__ sigma,   // (B,P,2)
    const float* __restrict__ velc,    // (B,K,2)
    const float* __restrict__ aw0, const float* __restrict__ ab0,
    const float* __restrict__ aw1, const float* __restrict__ ab1,
    const float* __restrict__ aw2, const float* __restrict__ ab2,
    const float* __restrict__ tw0, const float* __restrict__ tb0)
{
    __shared__ float s_aw0[6*64];
    __shared__ float s_ab0[64];
    __shared__ float s_aw1[64*64];   // row-major [j][i] (as stored)
    __shared__ float s_ab1[64];
    __shared__ float s_aw2[64];
    __shared__ float red[128];

    const int bx = blockIdx.x;               // 0..2175
    const int k1 = bx % K1;
    const int n  = (bx / K1) % Nn;
    const int b  = bx / (K1*Nn);
    const int t  = threadIdx.x;              // p

    for (int i = t; i < 6*64; i += 128) s_aw0[i] = aw0[i];
    if (t < 64) { s_ab0[t] = ab0[t]; s_aw2[t] = aw2[t]; s_ab1[t] = ab1[t]; }
    for (int i = t; i < 64*64; i += 128) s_aw1[i] = aw1[i];
    __syncthreads();

    const float x0 = phase[(b*Nn+n)*4 + 0];
    const float x1 = phase[(b*Nn+n)*4 + 1];
    float va0, va1;
    if (k1 == 0) { va0 = phase[(b*Nn+n)*4 + 2]; va1 = phase[(b*Nn+n)*4 + 3]; }
    else         { va0 = velc[(b*Kk + (k1-1))*2 + 0]; va1 = velc[(b*Kk + (k1-1))*2 + 1]; }
    const float inv = rsqrtf(va0*va0 + va1*va1 + 1e-16f);
    const float ag0 = va0*inv, ag1 = va1*inv;

    const float rx = x0 - posc[(b*Pp + t)*2 + 0];
    const float ry = x1 - posc[(b*Pp + t)*2 + 1];
    const float rd = sqrtf(rx*rx + ry*ry + 1e-16f);
    const float pl = rx*ag0 + ry*ag1;          // pos_local
    const float al = pl / (rd + 1e-8f);        // ang_local

    // layer 0: 6 -> 64
    float h0[64];
#pragma unroll
    for (int j = 0; j < 64; j++) {
        h0[j] = ftanh(s_ab0[j] + x0*s_aw0[0*64+j] + x1*s_aw0[1*64+j]
                              + va0*s_aw0[2*64+j] + va1*s_aw0[3*64+j]
                              + al*s_aw0[4*64+j] + pl*s_aw0[5*64+j]);
    }
    // layers 1+2 fused, paired over output i: 64 -> 64 (tanh) -> 1
    float logit = ab2[0];
#pragma unroll
    for (int g = 0; g < 4; g++) {           // 16 i's per group (8 pairs)
        ull acc[8];
#pragma unroll
        for (int p = 0; p < 8; p++) acc[p] = 0ull;
        for (int j = 0; j < 64; j++) {
            const ull hp = pack2(h0[j], h0[j]);
            const float* wrow = &s_aw1[j*64 + g*16];
            ulonglong2 wA = *reinterpret_cast<const ulonglong2*>(wrow + 0);
            ulonglong2 wB = *reinterpret_cast<const ulonglong2*>(wrow + 4);
            ulonglong2 wC = *reinterpret_cast<const ulonglong2*>(wrow + 8);
            ulonglong2 wD = *reinterpret_cast<const ulonglong2*>(wrow + 12);
            fma2(acc[0], hp, wA.x); fma2(acc[1], hp, wA.y);
            fma2(acc[2], hp, wB.x); fma2(acc[3], hp, wB.y);
            fma2(acc[4], hp, wC.x); fma2(acc[5], hp, wC.y);
            fma2(acc[6], hp, wD.x); fma2(acc[7], hp, wD.y);
        }
#pragma unroll
        for (int p = 0; p < 8; p++) {
            const int i = g*16 + p*2;
            float a0, a1; unpack2(acc[p], a0, a1);
            logit += ftanh(a0 + s_ab1[i])   * s_aw2[i]
                   + ftanh(a1 + s_ab1[i+1]) * s_aw2[i+1];
        }
    }

    // masked softmax over p
    float lg = (pl > 0.0f) ? logit : -1e30f;
    red[t] = lg; __syncthreads();
    for (int s = 64; s > 0; s >>= 1) { if (t < s) red[t] = fmaxf(red[t], red[t+s]); __syncthreads(); }
    const float mx = red[0]; __syncthreads();
    const float e = __expf(lg - mx);
    red[t] = e; __syncthreads();
    for (int s = 64; s > 0; s >>= 1) { if (t < s) red[t] += red[t+s]; __syncthreads(); }
    const float denom = red[0]; __syncthreads();
    const float aw = e / denom;

    const float sg0 = sigma[(b*Pp+t)*2 + 0];
    const float sg1 = sigma[(b*Pp+t)*2 + 1];
    red[t] = aw*sg0; __syncthreads();
    for (int s = 64; s > 0; s >>= 1) { if (t < s) red[t] += red[t+s]; __syncthreads(); }
    const float sum0 = red[0]; __syncthreads();
    red[t] = aw*sg1; __syncthreads();
    for (int s = 64; s > 0; s >>= 1) { if (t < s) red[t] += red[t+s]; __syncthreads(); }
    const float sum1 = red[0]; __syncthreads();

    const float c0 = __expf(-sum0);
    const float c1 = __expf(-sum1);

    // A[b,n,k1][0..255] = tb0 + x@tw0[0:2] + vall@tw0[2:4] + coeff@tw0[8:10]
    for (int tt = t; tt < TWd; tt += 128) {
        float a = tb0[tt]
                + x0*tw0[0*TWd+tt] + x1*tw0[1*TWd+tt]
                + va0*tw0[2*TWd+tt] + va1*tw0[3*TWd+tt]
                + c0*tw0[8*TWd+tt] + c1*tw0[9*TWd+tt];
        d_A[bx*TWd + tt] = a;
    }
}

// =====================================================================
// K_bm: Bm[b,m][0..255] = xp@tw0[4:6] + vp@tw0[6:8].  One block per (b,m).
// =====================================================================
__global__ void k_bm(const float* __restrict__ bcoords, const float* __restrict__ tw0)
{
    const int bm = blockIdx.x;   // b*64+m
    const int t  = threadIdx.x;  // 0..255
    const float xp0 = bcoords[bm*4+0], xp1 = bcoords[bm*4+1];
    const float vp0 = bcoords[bm*4+2], vp1 = bcoords[bm*4+3];
    d_Bm[bm*TWd + t] = xp0*tw0[4*TWd+t] + xp1*tw0[5*TWd+t]
                     + vp0*tw0[6*TWd+t] + vp1*tw0[7*TWd+t];
}

// =====================================================================
// K4: transport MLP (layers 1,2) + full scattering chain, fused.
// One block per (b, n, m-pair). 128 threads. The two m's ride in the f32x2
// lanes. Layer1: thread owns 2 columns (t, t+128) -> 34 accumulators so each
// broadcast LDS of h feeds 4x FMA2 (FMA-pipe bound, not LSU bound).
// =====================================================================
__global__ void __launch_bounds__(128) k4_main(
    const float* __restrict__ scat,   // (B,N,K)
    const float* __restrict__ sscat,  // (B,K,K)
    const float* __restrict__ vwt,    // (B,K)
    const float* __restrict__ tw1, const float* __restrict__ tb1,
    const float* __restrict__ tw2, const float* __restrict__ tb2,
    const float* __restrict__ sw0, const float* __restrict__ sb0,
    const float* __restrict__ sw1, const float* __restrict__ sb1,
    const float* __restrict__ out_w)
{
    __shared__ float buf[8704];      // h0(17x512) -> h1(17x512) -> [g(17x256)|rr(17x256)]
    __shared__ ull   ws2[272];       // row0 = rw_v dup-pairs, rows1..16 = rw_vs
    __shared__ float sres[256];      // 128 f32x2 pairs
    __shared__ float sred[256];      // 128 f32x2 pairs

    const int bx   = blockIdx.x;              // 0..4095
    const int pair = bx & 31;                 // m-pair index
    const int n    = (bx >> 5) & 31;
    const int b    = bx >> 10;
    const int t    = threadIdx.x;             // 0..127

    // scattering weight dup-pairs
    for (int i = t; i < 272; i += 128) {
        const int row = i >> 4, j = i & 15;
        float v = (row == 0) ? (1.0f - scat[(b*Nn+n)*Kk + j])
                             : (1.0f - sscat[b*256 + (row-1)*Kk + j]);
        v *= vwt[b*Kk + j];
        ws2[i] = pack2(v, v);
    }

    // ---- layer 0: h0[k][j][mi] = tanh(A[k][j] + Bm[m][j]), both lanes ----
    const float* Arow = d_A + (b*Nn + n)*K1*TWd;
    const float* bm0  = d_Bm + (b*Mm + pair*2 + 0)*TWd;
    const float* bm1  = bm0 + TWd;
    {
        const float b0a = bm0[t], b0b = bm0[t+128];
        const float b1a = bm1[t], b1b = bm1[t+128];
#pragma unroll
        for (int k = 0; k < K1; k++) {
            const float A0 = Arow[k*TWd + t];
            const float A1 = Arow[k*TWd + t + 128];
            *reinterpret_cast<ull*>(buf + k*512 + 2*t) =
                pack2(ftanh(A0 + b0a), ftanh(A0 + b1a));
            *reinterpret_cast<ull*>(buf + k*512 + 2*(t+128)) =
                pack2(ftanh(A1 + b0b), ftanh(A1 + b1b));
        }
    }
    __syncthreads();

    // ---- layer 1: h1 = tanh(h0 @ tw1 + tb1); thread owns cols t and t+128 ----
    {
        ull acc0[K1], acc1[K1];
#pragma unroll
        for (int k = 0; k < K1; k++) { acc0[k] = 0ull; acc1[k] = 0ull; }
        for (int j = 0; j < TWd; j += 4) {
            const float* w = tw1 + j*TWd + t;
            const float a0 = w[0],   a1 = w[TWd],     a2 = w[2*TWd],     a3 = w[3*TWd];
            const float c0 = w[128], c1 = w[TWd+128], c2 = w[2*TWd+128], c3 = w[3*TWd+128];
            const ull pa0 = pack2(a0,a0), pa1 = pack2(a1,a1), pa2 = pack2(a2,a2), pa3 = pack2(a3,a3);
            const ull pc0 = pack2(c0,c0), pc1 = pack2(c1,c1), pc2 = pack2(c2,c2), pc3 = pack2(c3,c3);
#pragma unroll
            for (int k = 0; k < K1; k++) {
                ulonglong2 ha = *reinterpret_cast<const ulonglong2*>(buf + k*512 + j*2);
                ulonglong2 hb = *reinterpret_cast<const ulonglong2*>(buf + k*512 + j*2 + 4);
                fma2(acc0[k], ha.x, pa0); fma2(acc0[k], ha.y, pa1);
                fma2(acc0[k], hb.x, pa2); fma2(acc0[k], hb.y, pa3);
                fma2(acc1[k], ha.x, pc0); fma2(acc1[k], ha.y, pc1);
                fma2(acc1[k], hb.x, pc2); fma2(acc1[k], hb.y, pc3);
            }
        }
        __syncthreads();   // all h0 reads done -> overwrite with h1
        const float t1a = tb1[t], t1b = tb1[t+128];
#pragma unroll
        for (int k = 0; k < K1; k++) {
            float x0, x1; unpack2(acc0[k], x0, x1);
            float y0, y1; unpack2(acc1[k], y0, y1);
            *reinterpret_cast<ull*>(buf + k*512 + 2*t) =
                pack2(ftanh(x0+t1a), ftanh(x1+t1a));
            *reinterpret_cast<ull*>(buf + k*512 + 2*(t+128)) =
                pack2(ftanh(y0+t1b), ftanh(y1+t1b));
        }
        __syncthreads();
    }

    // ---- layer 2: g = exp(tanh(h1 @ tw2 + tb2)); thread = col t (128 cols) ----
    {
        ull acc[K1];
#pragma unroll
        for (int k = 0; k < K1; k++) acc[k] = 0ull;
        for (int j = 0; j < TWd; j += 4) {
            const float* w = tw2 + j*Ww + t;
            const float w0 = w[0], w1 = w[Ww], w2 = w[2*Ww], w3 = w[3*Ww];
            const ull p0 = pack2(w0,w0), p1 = pack2(w1,w1), p2 = pack2(w2,w2), p3 = pack2(w3,w3);
#pragma unroll
            for (int k = 0; k < K1; k++) {
                ulonglong2 ha = *reinterpret_cast<const ulonglong2*>(buf + k*512 + j*2);
                ulonglong2 hb = *reinterpret_cast<const ulonglong2*>(buf + k*512 + j*2 + 4);
                fma2(acc[k], ha.x, p0); fma2(acc[k], ha.y, p1);
                fma2(acc[k], hb.x, p2); fma2(acc[k], hb.y, p3);
            }
        }
        __syncthreads();   // all h1 reads done -> buf becomes [g | rr]
        const float tb2c = tb2[t];
#pragma unroll
        for (int k = 0; k < K1; k++) {
            float x0, x1; unpack2(acc[k], x0, x1);
            *reinterpret_cast<ull*>(buf + k*256 + 2*t) =
                pack2(__expf(ftanh(x0+tb2c)), __expf(ftanh(x1+tb2c)));
        }
        __syncthreads();
    }

    // ---- stage 1: rr[0]=res_v, rr[1+i]=res2[i] from old g rows 1..16 ----
    {
        ull r[K1];
#pragma unroll
        for (int k = 0; k < K1; k++) r[k] = 0ull;
#pragma unroll
        for (int j = 0; j < Kk; j++) {
            const ull g2 = *reinterpret_cast<const ull*>(buf + (1+j)*256 + 2*t);
#pragma unroll
            for (int k = 0; k < K1; k++)
                fma2(r[k], g2, ws2[k*Kk + j]);
        }
#pragma unroll
        for (int k = 0; k < K1; k++)
            *reinterpret_cast<ull*>(buf + 4352 + k*256 + 2*t) = r[k];
        __syncthreads();
    }

    // ---- stage 2: g[row][t] += tanh(sum_w sw0[t][w]*rr[row][w] + sb0[t]) ----
    {
        ull s2[K1];
#pragma unroll
        for (int k = 0; k < K1; k++) s2[k] = 0ull;
        const float* swr = sw0 + t*Ww;
        for (int w = 0; w < Ww; w += 4) {
            const float4 s4 = *reinterpret_cast<const float4*>(swr + w);
            const ull p0 = pack2(s4.x,s4.x), p1 = pack2(s4.y,s4.y),
                      p2 = pack2(s4.z,s4.z), p3 = pack2(s4.w,s4.w);
#pragma unroll
            for (int k = 0; k < K1; k++) {
                ulonglong2 ra = *reinterpret_cast<const ulonglong2*>(buf + 4352 + k*256 + w*2);
                ulonglong2 rb = *reinterpret_cast<const ulonglong2*>(buf + 4352 + k*256 + w*2 + 4);
                fma2(s2[k], ra.x, p0); fma2(s2[k], ra.y, p1);
                fma2(s2[k], rb.x, p2); fma2(s2[k], rb.y, p3);
            }
        }
        const float sb0c = sb0[t];
#pragma unroll
        for (int k = 0; k < K1; k++) {
            float a0, a1; unpack2(s2[k], a0, a1);
            ull* gp = reinterpret_cast<ull*>(buf + k*256 + 2*t);
            float g0, g1; unpack2(*gp, g0, g1);
            *gp = pack2(g0 + ftanh(a0+sb0c), g1 + ftanh(a1+sb0c));
        }
        __syncthreads();
    }

    // ---- stage 3: resv2[t] = sum_k rw_v[k] * g'[1+k][t] ----
    {
        ull rv = 0ull;
#pragma unroll
        for (int k = 0; k < Kk; k++)
            fma2(rv, *reinterpret_cast<const ull*>(buf + (1+k)*256 + 2*t), ws2[k]);
        *reinterpret_cast<ull*>(sres + 2*t) = rv;
    }
    __syncthreads();

    // ---- stage 4: green = g'[0] + tanh(sw1[t][:]@resv2 + sb1); gdot reduce ----
    {
        ull sa = 0ull, sb = 0ull;
        const float* sw1r = sw1 + t*Ww;
        for (int w = 0; w < Ww; w += 8) {
            const float4 v4 = *reinterpret_cast<const float4*>(sw1r + w);
            const float4 u4 = *reinterpret_cast<const float4*>(sw1r + w + 4);
            ulonglong2 ra = *reinterpret_cast<const ulonglong2*>(sres + w*2);
            ulonglong2 rb = *reinterpret_cast<const ulonglong2*>(sres + w*2 + 4);
            ulonglong2 rc = *reinterpret_cast<const ulonglong2*>(sres + w*2 + 8);
            ulonglong2 rd = *reinterpret_cast<const ulonglong2*>(sres + w*2 + 12);
            fma2(sa, ra.x, pack2(v4.x,v4.x)); fma2(sb, ra.y, pack2(v4.y,v4.y));
            fma2(sa, rb.x, pack2(v4.z,v4.z)); fma2(sb, rb.y, pack2(v4.w,v4.w));
            fma2(sa, rc.x, pack2(u4.x,u4.x)); fma2(sb, rc.y, pack2(u4.y,u4.y));
            fma2(sa, rd.x, pack2(u4.z,u4.z)); fma2(sb, rd.y, pack2(u4.w,u4.w));
        }
        const ull tot = add2(sa, sb);
        float a0, a1; unpack2(tot, a0, a1);
        float v0, v1; unpack2(*reinterpret_cast<const ull*>(buf + 2*t), v0, v1);
        const float sb1c = sb1[t], ow = out_w[t];
        *reinterpret_cast<ull*>(sred + 2*t) =
            pack2((v0 + ftanh(a0+sb1c)) * ow, (v1 + ftanh(a1+sb1c)) * ow);
        __syncthreads();
        for (int s = 64; s > 0; s >>= 1) {
            if (t < s) {
                ull x = add2(*reinterpret_cast<const ull*>(sred + 2*t),
                             *reinterpret_cast<const ull*>(sred + 2*(t+s)));
                *reinterpret_cast<ull*>(sred + 2*t) = x;
            }
            __syncthreads();
        }
        if (t == 0) {
            float g0, g1; unpack2(*reinterpret_cast<const ull*>(sred), g0, g1);
            d_gdot[(b*Nn+n)*Mm + pair*2 + 0] = g0;
            d_gdot[(b*Nn+n)*Mm + pair*2 + 1] = g1;
        }
    }
}

// =====================================================================
// K6: out[b,n] = sum_m gdot[b,n,m] * boundary[b,m] * bweights[b,m]
// One block per (b,n), 64 threads.
// =====================================================================
__global__ void k6_final(const float* __restrict__ boundary,
                         const float* __restrict__ bweights,
                         float* __restrict__ out)
{
    __shared__ float s2[2];
    const int bn = blockIdx.x;          // 0..127
    const int b  = bn >> 5;
    const int t  = threadIdx.x;         // 0..63
    float v = d_gdot[bn*Mm + t] * boundary[b*Mm + t] * bweights[b*Mm + t];
#pragma unroll
    for (int o = 16; o > 0; o >>= 1) v += __shfl_down_sync(0xffffffffu, v, o);
    if ((t & 31) == 0) s2[t >> 5] = v;
    __syncthreads();
    if (t == 0) out[bn] = s2[0] + s2[1];
}

// =====================================================================
extern "C" void kernel_launch(void* const* d_in, const int* in_sizes, int n_in,
                              void* d_out, int out_size)
{
    const float* phase    = (const float*)d_in[0];
    const float* bcoords  = (const float*)d_in[1];
    const float* boundary = (const float*)d_in[2];
    const float* bweights = (const float*)d_in[3];
    const float* posc     = (const float*)d_in[4];
    const float* sigma    = (const float*)d_in[5];
    const float* velc     = (const float*)d_in[6];
    const float* vwt      = (const float*)d_in[7];
    const float* scat     = (const float*)d_in[8];
    const float* sscat    = (const float*)d_in[9];
    const float* aw0 = (const float*)d_in[10];
    const float* ab0 = (const float*)d_in[11];
    const float* aw1 = (const float*)d_in[12];
    const float* ab1 = (const float*)d_in[13];
    const float* aw2 = (const float*)d_in[14];
    const float* ab2 = (const float*)d_in[15];
    const float* tw0 = (const float*)d_in[16];
    const float* tb0 = (const float*)d_in[17];
    const float* tw1 = (const float*)d_in[18];
    const float* tb1 = (const float*)d_in[19];
    const float* tw2 = (const float*)d_in[20];
    const float* tb2 = (const float*)d_in[21];
    const float* sw0 = (const float*)d_in[22];
    const float* sb0 = (const float*)d_in[23];
    const float* sw1 = (const float*)d_in[24];
    const float* sb1 = (const float*)d_in[25];
    const float* ow  = (const float*)d_in[26];
    float* out = (float*)d_out;

    k1_attn<<<Bb*Nn*K1, 128>>>(phase, posc, sigma, velc,
                               aw0, ab0, aw1, ab1, aw2, ab2, tw0, tb0);
    k_bm<<<Bb*Mm, TWd>>>(bcoords, tw0);
    k4_main<<<Bb*Nn*(Mm/2), 128>>>(
        scat, sscat, vwt, tw1, tb1, tw2, tb2, sw0, sb0, sw1, sb1, ow);
    k6_final<<<Bb*Nn, 64>>>(boundary, bweights, out);
}